// round 11
// baseline (speedup 1.0000x reference)
#include <cuda_runtime.h>

// Problem dims (fixed by setup_inputs)
#define B_ 512
#define N_ 2048   // OUT
#define K_ 2048   // IN
#define NSTEPS 16
// cublasLt fp32 SGEMM sliced1x4 association: K split in 4 quarters, each a
// continuous ascending FFMA chain from zero; partials reduced sequentially
// (one RN add per slice, ascending slice order) -> folds at 512/1024/1536.
#define KC 512

// Scratch (static __device__ arrays: no allocation allowed)
__device__ float g_WrT[(size_t)N_ * N_];   // (W_rec*mask)^T, [k][j]
__device__ float g_WfcT[(size_t)K_ * N_];  // W_fc^T, [k][j]
__device__ float g_ff[B_ * N_];
__device__ float g_mem[B_ * N_];
__device__ float g_ath[B_ * N_];
__device__ float g_spkA[B_ * N_];
__device__ float g_spkB[B_ * N_];

// ---------------------------------------------------------------------------
// Transpose (optionally fused with integer mask multiply):
// dst[c*R + r] = src[r*C + c] * mask   (exact: mask is 0/1)
// ---------------------------------------------------------------------------
__global__ void transpose_mask_kernel(const float* __restrict__ src,
                                      const int* __restrict__ mask,
                                      float* __restrict__ dst, int R, int C) {
    __shared__ float tile[32][33];
    int c0 = blockIdx.x * 32, r0 = blockIdx.y * 32;
#pragma unroll
    for (int i = 0; i < 32; i += 8) {
        int r = r0 + threadIdx.y + i;
        int c = c0 + threadIdx.x;
        float v = src[(size_t)r * C + c];
        if (mask) v *= (float)mask[(size_t)r * C + c];
        tile[threadIdx.y + i][threadIdx.x] = v;
    }
    __syncthreads();
#pragma unroll
    for (int i = 0; i < 32; i += 8) {
        int r = c0 + threadIdx.y + i;  // dst row = src col
        int c = r0 + threadIdx.x;      // dst col = src row
        dst[(size_t)r * R + c] = tile[threadIdx.x][threadIdx.y + i];
    }
}

// ---------------------------------------------------------------------------
// Zero-init state + output
// ---------------------------------------------------------------------------
__global__ void init_zero_kernel(float* __restrict__ out) {
    int i = blockIdx.x * blockDim.x + threadIdx.x;
    if (i < B_ * N_) {
        g_mem[i]  = 0.0f;
        g_ath[i]  = 0.0f;
        g_spkA[i] = 0.0f;
        out[i]    = 0.0f;
    }
}

// ---------------------------------------------------------------------------
// fp32 SGEMM (NN): C[M=512,N=2048] = A[512,2048] * Bmat[2048,2048] + bias
// BM=64, BN=128, BK=16, per-thread 4x8, 256 threads, grid (16, 8) = 128 CTAs.
//
// Accumulation mirrors cublas sliced1x4:
//   part = FFMA chain over current K-quarter (ascending, from zero);
//   fold part into acc with one RN add at k = 512, 1024, 1536, 2048.
//
// FUSED=true: epilogue performs the SNN step update with per-op RN rounding.
// ---------------------------------------------------------------------------
#define BM 64
#define BN 128
#define BK 16

template <bool FUSED>
__global__ void __launch_bounds__(256)
sgemm_step(const float* __restrict__ A, const float* __restrict__ Bmat,
           const float* __restrict__ bias, float* __restrict__ Cout,
           const float* __restrict__ ff, float* __restrict__ spknext,
           float* __restrict__ ssum, const int* __restrict__ sw, int step) {
    if (FUSED) {
        if (step >= *sw) return;   // uniform: skip inactive timesteps
    }

    __shared__ float As[BK][BM];
    __shared__ float Bs[BK][BN];

    const int tid = threadIdx.x;
    const int bm = blockIdx.y * BM;
    const int bn = blockIdx.x * BN;

    // global -> shared load mapping
    const int arow = tid >> 2;            // 0..63
    const int acol = (tid & 3) << 2;      // 0,4,8,12 (float4)
    const int brow = tid >> 5;            // 0..7 (+8 second pass)
    const int bcol = (tid & 31) << 2;     // 0..124 (float4)

    // compute mapping
    const int ty = tid >> 4;              // 0..15 -> m block of 4
    const int tx = tid & 15;              // 0..15 -> n block of 8

    float acc[4][8];    // running total (folded slice partials)
    float part[4][8];   // current slice partial
#pragma unroll
    for (int i = 0; i < 4; i++)
#pragma unroll
        for (int j = 0; j < 8; j++) { acc[i][j] = 0.0f; part[i][j] = 0.0f; }

    const float* Ap = A + (size_t)(bm + arow) * K_ + acol;
    const float* Bp = Bmat + (size_t)brow * N_ + bn + bcol;

    for (int k0 = 0; k0 < K_; k0 += BK) {
        float4 av  = *(const float4*)(Ap + k0);
        float4 bv0 = *(const float4*)(Bp + (size_t)k0 * N_);
        float4 bv1 = *(const float4*)(Bp + (size_t)(k0 + 8) * N_);

        As[acol + 0][arow] = av.x;
        As[acol + 1][arow] = av.y;
        As[acol + 2][arow] = av.z;
        As[acol + 3][arow] = av.w;
        *(float4*)&Bs[brow][bcol]     = bv0;
        *(float4*)&Bs[brow + 8][bcol] = bv1;
        __syncthreads();

#pragma unroll
        for (int kk = 0; kk < BK; kk++) {
            float ar[4], br[8];
#pragma unroll
            for (int i = 0; i < 4; i++) ar[i] = As[kk][ty * 4 + i];
#pragma unroll
            for (int j = 0; j < 8; j++) br[j] = Bs[kk][tx * 8 + j];
#pragma unroll
            for (int i = 0; i < 4; i++)
#pragma unroll
                for (int j = 0; j < 8; j++)
                    part[i][j] = __fmaf_rn(ar[i], br[j], part[i][j]);
        }
        __syncthreads();

        // Fold slice partial at k = 512, 1024, 1536, 2048 (sequential slice
        // reduction, ascending order).
        const int knext = k0 + BK;
        if ((knext % KC) == 0) {
#pragma unroll
            for (int i = 0; i < 4; i++)
#pragma unroll
                for (int j = 0; j < 8; j++) {
                    acc[i][j]  = __fadd_rn(acc[i][j], part[i][j]);
                    part[i][j] = 0.0f;
                }
        }
    }

    // epilogue — every op individually RN-rounded (XLA per-HLO rounding;
    // no FMA contraction anywhere).
#pragma unroll
    for (int i = 0; i < 4; i++) {
        const int row = bm + ty * 4 + i;
#pragma unroll
        for (int j = 0; j < 8; j++) {
            const int col = bn + tx * 8 + j;
            const int idx = row * N_ + col;
            float mr = __fadd_rn(acc[i][j], bias[col]);
            if (FUSED) {
                float s = A[idx];          // previous spikes (exact {0,1,2})
                float m = g_mem[idx];
                float a = g_ath[idx];
                a = __fadd_rn(__fmul_rn(0.9f, a), __fmul_rn(0.5f, s));
                float mff = __fmul_rn(m, 0.2f);
                mff = __fmul_rn(mff, __fsub_rn(1.0f, s));
                mff = __fadd_rn(mff, ff[idx]);
                mff = __fsub_rn(mff, __fmul_rn(a, 0.2f));
                float sff = (mff > 0.5f) ? 1.0f : 0.0f;
                float sr  = (mr  > 0.5f) ? 1.0f : 0.0f;
                g_mem[idx] = __fadd_rn(mff, mr);
                g_ath[idx] = a;
                float sn = __fadd_rn(sff, sr);
                spknext[idx] = sn;
                ssum[idx] = __fadd_rn(ssum[idx], sn);
            } else {
                Cout[idx] = mr;
            }
        }
    }
}

// ---------------------------------------------------------------------------
// Launch: prep (transposes) -> init -> ff GEMM -> 16 x fused step GEMMs
// Inputs (metadata order): x, W_fc, b_fc, W_rec, b_rec, rec_mask, spike_window
// ---------------------------------------------------------------------------
extern "C" void kernel_launch(void* const* d_in, const int* in_sizes, int n_in,
                              void* d_out, int out_size) {
    const float* x        = (const float*)d_in[0];
    const float* W_fc     = (const float*)d_in[1];
    const float* b_fc     = (const float*)d_in[2];
    const float* W_rec    = (const float*)d_in[3];
    const float* b_rec    = (const float*)d_in[4];
    const int*   rec_mask = (const int*)d_in[5];
    const int*   sw       = (const int*)d_in[6];
    float*       out      = (float*)d_out;

    float *WrT, *WfcT, *ff, *spkA, *spkB;
    cudaGetSymbolAddress((void**)&WrT,  g_WrT);
    cudaGetSymbolAddress((void**)&WfcT, g_WfcT);
    cudaGetSymbolAddress((void**)&ff,   g_ff);
    cudaGetSymbolAddress((void**)&spkA, g_spkA);
    cudaGetSymbolAddress((void**)&spkB, g_spkB);

    dim3 tt(32, 8);
    // W_fc [OUT=N_, IN=K_] -> WfcT [K_, N_]
    transpose_mask_kernel<<<dim3(K_ / 32, N_ / 32), tt>>>(W_fc, nullptr, WfcT, N_, K_);
    // (W_rec * mask) [N_, N_] -> WrT [N_, N_]
    transpose_mask_kernel<<<dim3(N_ / 32, N_ / 32), tt>>>(W_rec, rec_mask, WrT, N_, N_);

    init_zero_kernel<<<(B_ * N_ + 255) / 256, 256>>>(out);

    dim3 gg(N_ / BN, B_ / BM);
    // ff = x @ W_fc^T + b_fc  (loop-invariant)
    sgemm_step<false><<<gg, 256>>>(x, WfcT, b_fc, ff, nullptr, nullptr, nullptr, sw, 0);

    // 16 recurrent steps, fused state update, ping-pong spike buffers
    for (int t = 0; t < NSTEPS; t++) {
        const float* sp = (t & 1) ? spkB : spkA;
        float*       sn = (t & 1) ? spkA : spkB;
        sgemm_step<true><<<gg, 256>>>(sp, WrT, b_rec, nullptr, ff, sn, out, sw, t);
    }
}

// round 12
// speedup vs baseline: 1.2012x; 1.2012x over previous
#include <cuda_runtime.h>

// Problem dims (fixed by setup_inputs)
#define B_ 512
#define N_ 2048   // OUT
#define K_ 2048   // IN
#define NSTEPS 16
// PROVEN (R11, rel_err = 0.0): reference association = fp32, K split in 4
// quarters of 512; each quarter a continuous ascending FFMA chain from zero;
// quarter-partials folded sequentially (one RN add each, ascending order).
#define KC 512
#define NSLICE (K_ / KC)   // 4

#define SZ (B_ * N_)

// Scratch (static __device__: no allocation allowed)
__device__ float g_WrT[(size_t)N_ * N_];   // (W_rec*mask)^T, [k][j]
__device__ float g_WfcT[(size_t)K_ * N_];  // W_fc^T, [k][j]
__device__ float g_part[(size_t)NSLICE * SZ];  // split-K partials (16MB)
__device__ float g_ff[SZ];
__device__ float g_mem[SZ];
__device__ float g_ath[SZ];
__device__ float g_spkA[SZ];
__device__ float g_spkB[SZ];

// ---------------------------------------------------------------------------
// Transpose (optionally fused with integer mask multiply):
// dst[c*R + r] = src[r*C + c] * mask   (exact: mask is 0/1)
// ---------------------------------------------------------------------------
__global__ void transpose_mask_kernel(const float* __restrict__ src,
                                      const int* __restrict__ mask,
                                      float* __restrict__ dst, int R, int C) {
    __shared__ float tile[32][33];
    int c0 = blockIdx.x * 32, r0 = blockIdx.y * 32;
#pragma unroll
    for (int i = 0; i < 32; i += 8) {
        int r = r0 + threadIdx.y + i;
        int c = c0 + threadIdx.x;
        float v = src[(size_t)r * C + c];
        if (mask) v *= (float)mask[(size_t)r * C + c];
        tile[threadIdx.y + i][threadIdx.x] = v;
    }
    __syncthreads();
#pragma unroll
    for (int i = 0; i < 32; i += 8) {
        int r = c0 + threadIdx.y + i;
        int c = r0 + threadIdx.x;
        dst[(size_t)r * R + c] = tile[threadIdx.x][threadIdx.y + i];
    }
}

__global__ void init_zero_kernel(float* __restrict__ out) {
    int i = blockIdx.x * blockDim.x + threadIdx.x;
    if (i < SZ) {
        g_mem[i]  = 0.0f;
        g_ath[i]  = 0.0f;
        g_spkA[i] = 0.0f;
        out[i]    = 0.0f;
    }
}

// ---------------------------------------------------------------------------
// Split-K slice SGEMM: for slice z, part = FFMA chain over k in
// [z*512, (z+1)*512), ascending, from zero — identical per-output arithmetic
// to the proven R11 kernel. BM=64, BN=128, BK=16, 4x8/thread, 256 threads,
// grid (16, 8, 4) = 512 CTAs, 2 CTAs/SM. Next k-tile prefetched into
// registers while computing the current one.
// ---------------------------------------------------------------------------
#define BM 64
#define BN 128
#define BK 16
#define NT (KC / BK)   // 32 k-tiles per slice

__global__ void __launch_bounds__(256, 2)
slice_gemm(const float* __restrict__ A, const float* __restrict__ Bmat,
           const int* __restrict__ sw, int step) {
    if (step >= *sw) return;   // uniform

    __shared__ float As[BK][BM];
    __shared__ float Bs[BK][BN];

    const int tid = threadIdx.x;
    const int bm = blockIdx.y * BM;
    const int bn = blockIdx.x * BN;
    const int z  = blockIdx.z;

    const int arow = tid >> 2;            // 0..63
    const int acol = (tid & 3) << 2;      // 0,4,8,12
    const int brow = tid >> 5;            // 0..7
    const int bcol = (tid & 31) << 2;     // 0..124

    const int ty = tid >> 4;              // m block of 4
    const int tx = tid & 15;              // n block of 8

    float part[4][8];
#pragma unroll
    for (int i = 0; i < 4; i++)
#pragma unroll
        for (int j = 0; j < 8; j++) part[i][j] = 0.0f;

    const float* Ap = A + (size_t)(bm + arow) * K_ + acol;
    const float* Bp = Bmat + (size_t)brow * N_ + bn + bcol;

    int k0 = z * KC;
    // prefetch tile 0
    float4 av  = *(const float4*)(Ap + k0);
    float4 bv0 = *(const float4*)(Bp + (size_t)k0 * N_);
    float4 bv1 = *(const float4*)(Bp + (size_t)(k0 + 8) * N_);

    for (int t = 0; t < NT; t++, k0 += BK) {
        As[acol + 0][arow] = av.x;
        As[acol + 1][arow] = av.y;
        As[acol + 2][arow] = av.z;
        As[acol + 3][arow] = av.w;
        *(float4*)&Bs[brow][bcol]     = bv0;
        *(float4*)&Bs[brow + 8][bcol] = bv1;
        __syncthreads();

        if (t + 1 < NT) {   // prefetch next tile into registers
            av  = *(const float4*)(Ap + k0 + BK);
            bv0 = *(const float4*)(Bp + (size_t)(k0 + BK) * N_);
            bv1 = *(const float4*)(Bp + (size_t)(k0 + BK + 8) * N_);
        }

#pragma unroll
        for (int kk = 0; kk < BK; kk++) {
            float ar[4], br[8];
#pragma unroll
            for (int i = 0; i < 4; i++) ar[i] = As[kk][ty * 4 + i];
#pragma unroll
            for (int j = 0; j < 8; j++) br[j] = Bs[kk][tx * 8 + j];
#pragma unroll
            for (int i = 0; i < 4; i++)
#pragma unroll
                for (int j = 0; j < 8; j++)
                    part[i][j] = __fmaf_rn(ar[i], br[j], part[i][j]);
        }
        __syncthreads();
    }

    float* Pz = g_part + (size_t)z * SZ;
#pragma unroll
    for (int i = 0; i < 4; i++) {
        const int row = bm + ty * 4 + i;
#pragma unroll
        for (int j = 0; j < 8; j++) {
            const int col = bn + tx * 8 + j;
            Pz[(size_t)row * N_ + col] = part[i][j];
        }
    }
}

// ---------------------------------------------------------------------------
// Reduce partials (ascending-order RN folds, identical to R11) + bias, then
// either write C (ff) or perform the fused SNN state update (per-op RN).
// ---------------------------------------------------------------------------
template <bool FUSED>
__global__ void __launch_bounds__(256)
reduce_step(const float* __restrict__ bias, float* __restrict__ Cout,
            const float* __restrict__ spkprev, float* __restrict__ spknext,
            const float* __restrict__ ff, float* __restrict__ ssum,
            const int* __restrict__ sw, int step) {
    if (FUSED) {
        if (step >= *sw) return;
    }
    const int i = blockIdx.x * blockDim.x + threadIdx.x;
    if (i >= SZ) return;
    const int col = i & (N_ - 1);

    // acc = rn(rn(rn(rn(0+P0)+P1)+P2)+P3) — exact R11 fold sequence
    float acc = 0.0f;
#pragma unroll
    for (int z = 0; z < NSLICE; z++)
        acc = __fadd_rn(acc, g_part[(size_t)z * SZ + i]);
    float mr = __fadd_rn(acc, bias[col]);

    if (FUSED) {
        float s = spkprev[i];
        float m = g_mem[i];
        float a = g_ath[i];
        a = __fadd_rn(__fmul_rn(0.9f, a), __fmul_rn(0.5f, s));
        float mff = __fmul_rn(m, 0.2f);
        mff = __fmul_rn(mff, __fsub_rn(1.0f, s));
        mff = __fadd_rn(mff, ff[i]);
        mff = __fsub_rn(mff, __fmul_rn(a, 0.2f));
        float sff = (mff > 0.5f) ? 1.0f : 0.0f;
        float sr  = (mr  > 0.5f) ? 1.0f : 0.0f;
        g_mem[i] = __fadd_rn(mff, mr);
        g_ath[i] = a;
        float sn = __fadd_rn(sff, sr);
        spknext[i] = sn;
        ssum[i] = __fadd_rn(ssum[i], sn);
    } else {
        Cout[i] = mr;
    }
}

// ---------------------------------------------------------------------------
// Launch. Inputs: x, W_fc, b_fc, W_rec, b_rec, rec_mask, spike_window
// ---------------------------------------------------------------------------
extern "C" void kernel_launch(void* const* d_in, const int* in_sizes, int n_in,
                              void* d_out, int out_size) {
    const float* x        = (const float*)d_in[0];
    const float* W_fc     = (const float*)d_in[1];
    const float* b_fc     = (const float*)d_in[2];
    const float* W_rec    = (const float*)d_in[3];
    const float* b_rec    = (const float*)d_in[4];
    const int*   rec_mask = (const int*)d_in[5];
    const int*   sw       = (const int*)d_in[6];
    float*       out      = (float*)d_out;

    float *WrT, *WfcT, *ff, *spkA, *spkB;
    cudaGetSymbolAddress((void**)&WrT,  g_WrT);
    cudaGetSymbolAddress((void**)&WfcT, g_WfcT);
    cudaGetSymbolAddress((void**)&ff,   g_ff);
    cudaGetSymbolAddress((void**)&spkA, g_spkA);
    cudaGetSymbolAddress((void**)&spkB, g_spkB);

    dim3 tt(32, 8);
    transpose_mask_kernel<<<dim3(K_ / 32, N_ / 32), tt>>>(W_fc, nullptr, WfcT, N_, K_);
    transpose_mask_kernel<<<dim3(N_ / 32, N_ / 32), tt>>>(W_rec, rec_mask, WrT, N_, N_);

    init_zero_kernel<<<(SZ + 255) / 256, 256>>>(out);

    dim3 gg(N_ / BN, B_ / BM, NSLICE);   // (16, 8, 4) = 512 CTAs
    const int rb = (SZ + 255) / 256;

    // ff = x @ W_fc^T + b_fc  (loop-invariant)
    slice_gemm<<<gg, 256>>>(x, WfcT, sw, 0);
    reduce_step<false><<<rb, 256>>>(b_fc, ff, nullptr, nullptr, nullptr, nullptr, sw, 0);

    // 16 recurrent steps: split-K GEMM + fused reduce/SNN, ping-pong spikes
    for (int t = 0; t < NSTEPS; t++) {
        const float* sp = (t & 1) ? spkB : spkA;
        float*       sn = (t & 1) ? spkA : spkB;
        slice_gemm<<<gg, 256>>>(sp, WrT, sw, t);
        reduce_step<true><<<rb, 256>>>(b_rec, nullptr, sp, sn, ff, out, sw, t);
    }
}

// round 13
// speedup vs baseline: 1.2817x; 1.0670x over previous
#include <cuda_runtime.h>

// Problem dims (fixed by setup_inputs)
#define B_ 512
#define N_ 2048   // OUT
#define K_ 2048   // IN
#define NSTEPS 16
// PROVEN (R11, rel_err = 0.0): reference association = fp32, K split in 4
// quarters of 512; each quarter a continuous ascending FFMA chain from zero;
// quarter-partials folded sequentially (one RN add each, ascending order).
#define KC 512
#define NSLICE (K_ / KC)   // 4

#define SZ (B_ * N_)

// Scratch (static __device__: no allocation allowed)
__device__ float g_WrT[(size_t)N_ * N_];   // (W_rec*mask)^T, [k][j]
__device__ float g_WfcT[(size_t)K_ * N_];  // W_fc^T, [k][j]
__device__ float g_part[(size_t)NSLICE * SZ];  // split-K partials (16MB)
__device__ float g_ff[SZ];
__device__ float g_mem[SZ];
__device__ float g_ath[SZ];
__device__ float g_spkA[SZ];
__device__ float g_spkB[SZ];

// ---------------------------------------------------------------------------
// Transpose (optionally fused with integer mask multiply):
// dst[c*R + r] = src[r*C + c] * mask   (exact: mask is 0/1)
// ---------------------------------------------------------------------------
__global__ void transpose_mask_kernel(const float* __restrict__ src,
                                      const int* __restrict__ mask,
                                      float* __restrict__ dst, int R, int C) {
    __shared__ float tile[32][33];
    int c0 = blockIdx.x * 32, r0 = blockIdx.y * 32;
#pragma unroll
    for (int i = 0; i < 32; i += 8) {
        int r = r0 + threadIdx.y + i;
        int c = c0 + threadIdx.x;
        float v = src[(size_t)r * C + c];
        if (mask) v *= (float)mask[(size_t)r * C + c];
        tile[threadIdx.y + i][threadIdx.x] = v;
    }
    __syncthreads();
#pragma unroll
    for (int i = 0; i < 32; i += 8) {
        int r = c0 + threadIdx.y + i;
        int c = r0 + threadIdx.x;
        dst[(size_t)r * R + c] = tile[threadIdx.x][threadIdx.y + i];
    }
}

__global__ void init_zero_kernel(float* __restrict__ out) {
    int i = blockIdx.x * blockDim.x + threadIdx.x;
    if (i < SZ) {
        g_mem[i]  = 0.0f;
        g_ath[i]  = 0.0f;
        g_spkA[i] = 0.0f;
        out[i]    = 0.0f;
    }
}

// ---------------------------------------------------------------------------
// Split-K slice SGEMM: for slice z, part = FFMA chain over k in
// [z*512, (z+1)*512), ascending, from zero — per-output arithmetic identical
// to R11 (rel_err 0.0). BM=64, BN=128, BK=16, 4x8/thread, 256 threads,
// grid (16, 8, 4) = 512 CTAs, 2 CTAs/SM.
// Perf: double-buffered SMEM (ONE sync per k-tile), gmem prefetch overlapped
// with compute, and LDS.128 fragment loads (removes the 4-way bank conflict
// the R12 profile showed: L1 75% / fma 29%).
// ---------------------------------------------------------------------------
#define BM 64
#define BN 128
#define BK 16
#define NT (KC / BK)   // 32 k-tiles per slice

__global__ void __launch_bounds__(256, 2)
slice_gemm(const float* __restrict__ A, const float* __restrict__ Bmat,
           const int* __restrict__ sw, int step) {
    if (step >= *sw) return;   // uniform

    __shared__ float As[2][BK][BM];
    __shared__ float Bs[2][BK][BN];

    const int tid = threadIdx.x;
    const int bm = blockIdx.y * BM;
    const int bn = blockIdx.x * BN;
    const int z  = blockIdx.z;

    const int arow = tid >> 2;            // 0..63
    const int acol = (tid & 3) << 2;      // 0,4,8,12
    const int brow = tid >> 5;            // 0..7
    const int bcol = (tid & 31) << 2;     // 0..124

    const int ty = tid >> 4;              // m block of 4
    const int tx = tid & 15;              // n block of 8

    float part[4][8];
#pragma unroll
    for (int i = 0; i < 4; i++)
#pragma unroll
        for (int j = 0; j < 8; j++) part[i][j] = 0.0f;

    const float* Ap = A + (size_t)(bm + arow) * K_ + acol + z * KC;
    const float* Bp = Bmat + (size_t)(brow + z * KC) * N_ + bn + bcol;

    // prefetch tile 0
    float4 av  = *(const float4*)(Ap);
    float4 bv0 = *(const float4*)(Bp);
    float4 bv1 = *(const float4*)(Bp + 8 * N_);

    for (int t = 0; t < NT; t++) {
        const int buf = t & 1;
        // stage current tile
        As[buf][acol + 0][arow] = av.x;
        As[buf][acol + 1][arow] = av.y;
        As[buf][acol + 2][arow] = av.z;
        As[buf][acol + 3][arow] = av.w;
        *(float4*)&Bs[buf][brow][bcol]     = bv0;
        *(float4*)&Bs[buf][brow + 8][bcol] = bv1;
        __syncthreads();

        // prefetch next tile (latency overlapped with compute below)
        if (t + 1 < NT) {
            const int kn = (t + 1) * BK;
            av  = *(const float4*)(Ap + kn);
            bv0 = *(const float4*)(Bp + (size_t)kn * N_);
            bv1 = *(const float4*)(Bp + (size_t)(kn + 8) * N_);
        }

#pragma unroll
        for (int kk = 0; kk < BK; kk++) {
            const float4 a4  = *(const float4*)&As[buf][kk][ty * 4];
            const float4 b4a = *(const float4*)&Bs[buf][kk][tx * 8];
            const float4 b4b = *(const float4*)&Bs[buf][kk][tx * 8 + 4];
            const float ar[4] = { a4.x, a4.y, a4.z, a4.w };
            const float br[8] = { b4a.x, b4a.y, b4a.z, b4a.w,
                                  b4b.x, b4b.y, b4b.z, b4b.w };
#pragma unroll
            for (int i = 0; i < 4; i++)
#pragma unroll
                for (int j = 0; j < 8; j++)
                    part[i][j] = __fmaf_rn(ar[i], br[j], part[i][j]);
        }
        // NOTE: no second sync needed — next iteration writes the other buffer,
        // and the sync at its top orders those writes vs. this compute.
        __syncthreads();
    }

    float* Pz = g_part + (size_t)z * SZ;
#pragma unroll
    for (int i = 0; i < 4; i++) {
        const int row = bm + ty * 4 + i;
#pragma unroll
        for (int j = 0; j < 8; j += 4) {
            const int col = bn + tx * 8 + j;
            float4 v = { part[i][j], part[i][j + 1], part[i][j + 2], part[i][j + 3] };
            *(float4*)&Pz[(size_t)row * N_ + col] = v;
        }
    }
}

// ---------------------------------------------------------------------------
// Reduce partials (ascending-order RN folds, identical to R11) + bias, then
// either write C (ff) or perform the fused SNN state update (per-op RN).
// ---------------------------------------------------------------------------
template <bool FUSED>
__global__ void __launch_bounds__(256)
reduce_step(const float* __restrict__ bias, float* __restrict__ Cout,
            const float* __restrict__ spkprev, float* __restrict__ spknext,
            const float* __restrict__ ff, float* __restrict__ ssum,
            const int* __restrict__ sw, int step) {
    if (FUSED) {
        if (step >= *sw) return;
    }
    const int i = blockIdx.x * blockDim.x + threadIdx.x;
    if (i >= SZ) return;
    const int col = i & (N_ - 1);

    // acc = rn(rn(rn(rn(0+P0)+P1)+P2)+P3) — exact R11 fold sequence
    float acc = 0.0f;
#pragma unroll
    for (int zz = 0; zz < NSLICE; zz++)
        acc = __fadd_rn(acc, g_part[(size_t)zz * SZ + i]);
    float mr = __fadd_rn(acc, bias[col]);

    if (FUSED) {
        float s = spkprev[i];
        float m = g_mem[i];
        float a = g_ath[i];
        a = __fadd_rn(__fmul_rn(0.9f, a), __fmul_rn(0.5f, s));
        float mff = __fmul_rn(m, 0.2f);
        mff = __fmul_rn(mff, __fsub_rn(1.0f, s));
        mff = __fadd_rn(mff, ff[i]);
        mff = __fsub_rn(mff, __fmul_rn(a, 0.2f));
        float sff = (mff > 0.5f) ? 1.0f : 0.0f;
        float sr  = (mr  > 0.5f) ? 1.0f : 0.0f;
        g_mem[i] = __fadd_rn(mff, mr);
        g_ath[i] = a;
        float sn = __fadd_rn(sff, sr);
        spknext[i] = sn;
        ssum[i] = __fadd_rn(ssum[i], sn);
    } else {
        Cout[i] = mr;
    }
}

// ---------------------------------------------------------------------------
// Launch. Inputs: x, W_fc, b_fc, W_rec, b_rec, rec_mask, spike_window
// ---------------------------------------------------------------------------
extern "C" void kernel_launch(void* const* d_in, const int* in_sizes, int n_in,
                              void* d_out, int out_size) {
    const float* x        = (const float*)d_in[0];
    const float* W_fc     = (const float*)d_in[1];
    const float* b_fc     = (const float*)d_in[2];
    const float* W_rec    = (const float*)d_in[3];
    const float* b_rec    = (const float*)d_in[4];
    const int*   rec_mask = (const int*)d_in[5];
    const int*   sw       = (const int*)d_in[6];
    float*       out      = (float*)d_out;

    float *WrT, *WfcT, *ff, *spkA, *spkB;
    cudaGetSymbolAddress((void**)&WrT,  g_WrT);
    cudaGetSymbolAddress((void**)&WfcT, g_WfcT);
    cudaGetSymbolAddress((void**)&ff,   g_ff);
    cudaGetSymbolAddress((void**)&spkA, g_spkA);
    cudaGetSymbolAddress((void**)&spkB, g_spkB);

    dim3 tt(32, 8);
    transpose_mask_kernel<<<dim3(K_ / 32, N_ / 32), tt>>>(W_fc, nullptr, WfcT, N_, K_);
    transpose_mask_kernel<<<dim3(N_ / 32, N_ / 32), tt>>>(W_rec, rec_mask, WrT, N_, N_);

    init_zero_kernel<<<(SZ + 255) / 256, 256>>>(out);

    dim3 gg(N_ / BN, B_ / BM, NSLICE);   // (16, 8, 4) = 512 CTAs
    const int rb = (SZ + 255) / 256;

    // ff = x @ W_fc^T + b_fc  (loop-invariant)
    slice_gemm<<<gg, 256>>>(x, WfcT, sw, 0);
    reduce_step<false><<<rb, 256>>>(b_fc, ff, nullptr, nullptr, nullptr, nullptr, sw, 0);

    // 16 recurrent steps: split-K GEMM + fused reduce/SNN, ping-pong spikes
    for (int t = 0; t < NSTEPS; t++) {
        const float* sp = (t & 1) ? spkB : spkA;
        float*       sn = (t & 1) ? spkA : spkB;
        slice_gemm<<<gg, 256>>>(sp, WrT, sw, t);
        reduce_step<true><<<rb, 256>>>(b_rec, nullptr, sp, sn, ff, out, sw, t);
    }
}

// round 14
// speedup vs baseline: 2.0385x; 1.5905x over previous
#include <cuda_runtime.h>

// Problem dims (fixed by setup_inputs)
#define B_ 512
#define N_ 2048   // OUT
#define K_ 2048   // IN
#define NSTEPS 16
// PROVEN (R11, rel_err = 0.0): reference association = fp32, K split in 4
// quarters of 512; each quarter a continuous ascending FFMA chain from zero;
// quarter-partials folded sequentially (one RN add each, ascending order).
#define KC 512
#define NSLICE (K_ / KC)   // 4

#define SZ (B_ * N_)

// Scratch (static __device__: no allocation allowed)
__device__ float g_WrT[(size_t)N_ * N_];   // (W_rec*mask)^T, [k][j]
__device__ float g_WfcT[(size_t)K_ * N_];  // W_fc^T, [k][j]
__device__ float g_part[(size_t)NSLICE * SZ];  // split-K partials (16MB)
__device__ float g_ff[SZ];
__device__ float g_mem[SZ];
__device__ float g_ath[SZ];
__device__ float g_spkA[SZ];
__device__ float g_spkB[SZ];

// ---------------------------------------------------------------------------
// Transpose (optionally fused with integer mask multiply)
// ---------------------------------------------------------------------------
__global__ void transpose_mask_kernel(const float* __restrict__ src,
                                      const int* __restrict__ mask,
                                      float* __restrict__ dst, int R, int C) {
    __shared__ float tile[32][33];
    int c0 = blockIdx.x * 32, r0 = blockIdx.y * 32;
#pragma unroll
    for (int i = 0; i < 32; i += 8) {
        int r = r0 + threadIdx.y + i;
        int c = c0 + threadIdx.x;
        float v = src[(size_t)r * C + c];
        if (mask) v *= (float)mask[(size_t)r * C + c];
        tile[threadIdx.y + i][threadIdx.x] = v;
    }
    __syncthreads();
#pragma unroll
    for (int i = 0; i < 32; i += 8) {
        int r = c0 + threadIdx.y + i;
        int c = r0 + threadIdx.x;
        dst[(size_t)r * R + c] = tile[threadIdx.x][threadIdx.y + i];
    }
}

__global__ void init_zero_kernel(float* __restrict__ out) {
    int i = blockIdx.x * blockDim.x + threadIdx.x;
    if (i < SZ) {
        g_mem[i]  = 0.0f;
        g_ath[i]  = 0.0f;
        g_spkA[i] = 0.0f;
        out[i]    = 0.0f;
    }
}

// ---------------------------------------------------------------------------
// Split-K slice SGEMM, 8x8 per-thread, conflict-free fragment LDS.
// BM=128, BN=128, BK=16, 256 threads, grid (16, 4, 4) = 256 CTAs, 2 CTAs/SM.
// Per output (m,n), slice z: part = FFMA chain over k ascending in
// [z*512, (z+1)*512) from zero — bit-identical to R11/R13.
// ---------------------------------------------------------------------------
#define BM 128
#define BN 128
#define BK 16
#define NT (KC / BK)   // 32 k-tiles per slice
#define ASTR 132       // padded smem row stride (floats)
#define BSTR 132

__global__ void __launch_bounds__(256, 2)
slice_gemm(const float* __restrict__ A, const float* __restrict__ Bmat,
           const int* __restrict__ sw, int step) {
    if (step >= *sw) return;   // uniform

    __shared__ float As[2][BK][ASTR];
    __shared__ float Bs[2][BK][BSTR];

    const int tid = threadIdx.x;
    const int wid = tid >> 5;
    const int lane = tid & 31;
    const int lm = lane & 7;         // 0..7
    const int ln = lane >> 3;        // 0..3
    const int wm = (wid & 1) * 64;   // warp m offset
    const int wn = (wid >> 1) * 32;  // warp n offset
    const int bm = blockIdx.y * BM;
    const int bn = blockIdx.x * BN;
    const int z  = blockIdx.z;
    const int kbase = z * KC;

    // fragment smem column bases
    const int m0 = wm + lm * 4;
    const int m1 = wm + 32 + lm * 4;
    const int n0 = wn + ln * 4;
    const int n1 = wn + 16 + ln * 4;

    float acc[2][2][4][4];
#pragma unroll
    for (int mi = 0; mi < 2; mi++)
#pragma unroll
        for (int ni = 0; ni < 2; ni++)
#pragma unroll
            for (int i = 0; i < 4; i++)
#pragma unroll
                for (int j = 0; j < 4; j++) acc[mi][ni][i][j] = 0.0f;

    // staging mapping: 512 float4 for A (2/thread), 512 for B (2/thread)
    int arow[2], ac4[2], bkk[2], bn4[2];
    const float* Aptr[2];
    const float* Bptr[2];
#pragma unroll
    for (int f = 0; f < 2; f++) {
        const int ida = tid + 256 * f;
        arow[f] = ida >> 2;              // 0..127 (m)
        ac4[f]  = (ida & 3) << 2;        // k offset 0,4,8,12
        Aptr[f] = A + (size_t)(bm + arow[f]) * K_ + kbase + ac4[f];
        const int idb = tid + 256 * f;
        bkk[f] = idb >> 5;               // 0..15 (k)
        bn4[f] = (idb & 31) << 2;        // 0..124 (n)
        Bptr[f] = Bmat + (size_t)(kbase + bkk[f]) * N_ + bn + bn4[f];
    }

    // prefetch tile 0
    float4 av[2], bv[2];
#pragma unroll
    for (int f = 0; f < 2; f++) {
        av[f] = *(const float4*)(Aptr[f]);
        bv[f] = *(const float4*)(Bptr[f]);
    }

    for (int t = 0; t < NT; t++) {
        const int buf = t & 1;
        // stage current tile (A transposed to [k][m])
#pragma unroll
        for (int f = 0; f < 2; f++) {
            As[buf][ac4[f] + 0][arow[f]] = av[f].x;
            As[buf][ac4[f] + 1][arow[f]] = av[f].y;
            As[buf][ac4[f] + 2][arow[f]] = av[f].z;
            As[buf][ac4[f] + 3][arow[f]] = av[f].w;
            *(float4*)&Bs[buf][bkk[f]][bn4[f]] = bv[f];
        }
        __syncthreads();

        // prefetch next tile (overlapped with compute)
        if (t + 1 < NT) {
            const int kn = (t + 1) * BK;
#pragma unroll
            for (int f = 0; f < 2; f++) {
                av[f] = *(const float4*)(Aptr[f] + kn);
                bv[f] = *(const float4*)(Bptr[f] + (size_t)kn * N_);
            }
        }

#pragma unroll
        for (int kk = 0; kk < BK; kk++) {
            const float4 a0 = *(const float4*)&As[buf][kk][m0];
            const float4 a1 = *(const float4*)&As[buf][kk][m1];
            const float4 b0 = *(const float4*)&Bs[buf][kk][n0];
            const float4 b1 = *(const float4*)&Bs[buf][kk][n1];
            const float am[2][4] = { { a0.x, a0.y, a0.z, a0.w },
                                     { a1.x, a1.y, a1.z, a1.w } };
            const float bn_[2][4] = { { b0.x, b0.y, b0.z, b0.w },
                                      { b1.x, b1.y, b1.z, b1.w } };
#pragma unroll
            for (int mi = 0; mi < 2; mi++)
#pragma unroll
                for (int ni = 0; ni < 2; ni++)
#pragma unroll
                    for (int i = 0; i < 4; i++)
#pragma unroll
                        for (int j = 0; j < 4; j++)
                            acc[mi][ni][i][j] =
                                __fmaf_rn(am[mi][i], bn_[ni][j], acc[mi][ni][i][j]);
        }
        __syncthreads();
    }

    float* Pz = g_part + (size_t)z * SZ;
#pragma unroll
    for (int mi = 0; mi < 2; mi++) {
#pragma unroll
        for (int i = 0; i < 4; i++) {
            const int row = bm + wm + mi * 32 + lm * 4 + i;
#pragma unroll
            for (int ni = 0; ni < 2; ni++) {
                const int col = bn + wn + ni * 16 + ln * 4;
                float4 v = { acc[mi][ni][i][0], acc[mi][ni][i][1],
                             acc[mi][ni][i][2], acc[mi][ni][i][3] };
                *(float4*)&Pz[(size_t)row * N_ + col] = v;
            }
        }
    }
}

// ---------------------------------------------------------------------------
// Reduce partials (ascending-order RN folds, identical to R11) + bias, then
// either write C (ff) or perform the fused SNN state update (per-op RN).
// ---------------------------------------------------------------------------
template <bool FUSED>
__global__ void __launch_bounds__(256)
reduce_step(const float* __restrict__ bias, float* __restrict__ Cout,
            const float* __restrict__ spkprev, float* __restrict__ spknext,
            const float* __restrict__ ff, float* __restrict__ ssum,
            const int* __restrict__ sw, int step) {
    if (FUSED) {
        if (step >= *sw) return;
    }
    const int i = blockIdx.x * blockDim.x + threadIdx.x;
    if (i >= SZ) return;
    const int col = i & (N_ - 1);

    float acc = 0.0f;
#pragma unroll
    for (int zz = 0; zz < NSLICE; zz++)
        acc = __fadd_rn(acc, g_part[(size_t)zz * SZ + i]);
    float mr = __fadd_rn(acc, bias[col]);

    if (FUSED) {
        float s = spkprev[i];
        float m = g_mem[i];
        float a = g_ath[i];
        a = __fadd_rn(__fmul_rn(0.9f, a), __fmul_rn(0.5f, s));
        float mff = __fmul_rn(m, 0.2f);
        mff = __fmul_rn(mff, __fsub_rn(1.0f, s));
        mff = __fadd_rn(mff, ff[i]);
        mff = __fsub_rn(mff, __fmul_rn(a, 0.2f));
        float sff = (mff > 0.5f) ? 1.0f : 0.0f;
        float sr  = (mr  > 0.5f) ? 1.0f : 0.0f;
        g_mem[i] = __fadd_rn(mff, mr);
        g_ath[i] = a;
        float sn = __fadd_rn(sff, sr);
        spknext[i] = sn;
        ssum[i] = __fadd_rn(ssum[i], sn);
    } else {
        Cout[i] = mr;
    }
}

// ---------------------------------------------------------------------------
// Launch. Inputs: x, W_fc, b_fc, W_rec, b_rec, rec_mask, spike_window
// ---------------------------------------------------------------------------
extern "C" void kernel_launch(void* const* d_in, const int* in_sizes, int n_in,
                              void* d_out, int out_size) {
    const float* x        = (const float*)d_in[0];
    const float* W_fc     = (const float*)d_in[1];
    const float* b_fc     = (const float*)d_in[2];
    const float* W_rec    = (const float*)d_in[3];
    const float* b_rec    = (const float*)d_in[4];
    const int*   rec_mask = (const int*)d_in[5];
    const int*   sw       = (const int*)d_in[6];
    float*       out      = (float*)d_out;

    float *WrT, *WfcT, *ff, *spkA, *spkB;
    cudaGetSymbolAddress((void**)&WrT,  g_WrT);
    cudaGetSymbolAddress((void**)&WfcT, g_WfcT);
    cudaGetSymbolAddress((void**)&ff,   g_ff);
    cudaGetSymbolAddress((void**)&spkA, g_spkA);
    cudaGetSymbolAddress((void**)&spkB, g_spkB);

    dim3 tt(32, 8);
    transpose_mask_kernel<<<dim3(K_ / 32, N_ / 32), tt>>>(W_fc, nullptr, WfcT, N_, K_);
    transpose_mask_kernel<<<dim3(N_ / 32, N_ / 32), tt>>>(W_rec, rec_mask, WrT, N_, N_);

    init_zero_kernel<<<(SZ + 255) / 256, 256>>>(out);

    dim3 gg(N_ / BN, B_ / BM, NSLICE);   // (16, 4, 4) = 256 CTAs
    const int rb = (SZ + 255) / 256;

    // ff = x @ W_fc^T + b_fc  (loop-invariant)
    slice_gemm<<<gg, 256>>>(x, WfcT, sw, 0);
    reduce_step<false><<<rb, 256>>>(b_fc, ff, nullptr, nullptr, nullptr, nullptr, sw, 0);

    // 16 recurrent steps: split-K GEMM + fused reduce/SNN, ping-pong spikes
    for (int t = 0; t < NSTEPS; t++) {
        const float* sp = (t & 1) ? spkB : spkA;
        float*       sn = (t & 1) ? spkA : spkB;
        slice_gemm<<<gg, 256>>>(sp, WrT, sw, t);
        reduce_step<true><<<rb, 256>>>(b_rec, nullptr, sp, sn, ff, out, sw, t);
    }
}

// round 15
// speedup vs baseline: 2.1819x; 1.0703x over previous
#include <cuda_runtime.h>
#include <cstdint>

// Problem dims (fixed by setup_inputs)
#define B_ 512
#define N_ 2048   // OUT
#define K_ 2048   // IN
#define NSTEPS 16
// PROVEN (R11, rel_err = 0.0): reference association = fp32, K split in 4
// quarters of 512; each quarter a continuous ascending FFMA chain from zero;
// quarter-partials folded sequentially (one RN add each, ascending order).
#define KC 512
#define NSLICE (K_ / KC)   // 4
#define SZ (B_ * N_)

// GEMM tiling
#define BM 128
#define BN 128
#define BK 32
#define NT (KC / BK)       // 16 k-tiles per slice
#define STR 132            // smem row stride (floats), padded
#define SMEM_GEMM (2 * 2 * BK * STR * 4)   // A+B double-buffered = 67584 B

// Scratch (static __device__: no allocation allowed)
__device__ float g_WrT[(size_t)N_ * N_];   // (W_rec*mask)^T [k][n]
__device__ float g_WfcT[(size_t)K_ * N_];  // W_fc^T [k][n]
__device__ float g_xT[(size_t)K_ * B_];    // x^T [k][m]
__device__ float g_spkT[(size_t)N_ * B_];  // spk^T [k][m] (GEMM A operand)
__device__ float g_part[(size_t)NSLICE * SZ];  // split-K partials (16MB)
__device__ float g_ff[SZ];
__device__ float g_mem[SZ];
__device__ float g_ath[SZ];
__device__ float g_spk[SZ];                // row-major spikes (state)

// ---------------------------------------------------------------------------
// Transpose (optionally fused with integer mask multiply)
// ---------------------------------------------------------------------------
__global__ void transpose_mask_kernel(const float* __restrict__ src,
                                      const int* __restrict__ mask,
                                      float* __restrict__ dst, int R, int C) {
    __shared__ float tile[32][33];
    int c0 = blockIdx.x * 32, r0 = blockIdx.y * 32;
#pragma unroll
    for (int i = 0; i < 32; i += 8) {
        int r = r0 + threadIdx.y + i;
        int c = c0 + threadIdx.x;
        float v = src[(size_t)r * C + c];
        if (mask) v *= (float)mask[(size_t)r * C + c];
        tile[threadIdx.y + i][threadIdx.x] = v;
    }
    __syncthreads();
#pragma unroll
    for (int i = 0; i < 32; i += 8) {
        int r = c0 + threadIdx.y + i;
        int c = r0 + threadIdx.x;
        dst[(size_t)r * R + c] = tile[threadIdx.x][threadIdx.y + i];
    }
}

__global__ void init_zero_kernel(float* __restrict__ out) {
    int i = blockIdx.x * blockDim.x + threadIdx.x;
    if (i < SZ) {
        g_mem[i] = 0.0f;
        g_ath[i] = 0.0f;
        g_spk[i] = 0.0f;
        out[i]   = 0.0f;
    }
}

// ---------------------------------------------------------------------------
// cp.async helpers
// ---------------------------------------------------------------------------
static __device__ __forceinline__ void cpa16(uint32_t dst, const float* src) {
    asm volatile("cp.async.cg.shared.global [%0], [%1], 16;"
                 :: "r"(dst), "l"(src));
}
static __device__ __forceinline__ void cpa_commit() {
    asm volatile("cp.async.commit_group;" ::: "memory");
}

// ---------------------------------------------------------------------------
// Split-K slice SGEMM (both operands pre-transposed to [k][.]):
//   part(m,n,z) = FFMA chain over k ascending in [z*512,(z+1)*512) from zero.
// BM=BN=128, BK=32, 8x8/thread, 256 threads, grid (16,4,4)=256 CTAs,
// 2 CTAs/SM. cp.async double-buffered staging; conflict-free LDS.128 frags.
// ---------------------------------------------------------------------------
__global__ void __launch_bounds__(256, 2)
slice_gemm(const float* __restrict__ AT, const float* __restrict__ BT,
           const int* __restrict__ sw, int step) {
    if (step >= *sw) return;   // uniform

    extern __shared__ float sm[];
    // layout: As[2][BK][STR], then Bs[2][BK][STR]
    const uint32_t smb = (uint32_t)__cvta_generic_to_shared(sm);
    const int tid = threadIdx.x;
    const int wid = tid >> 5;
    const int lane = tid & 31;
    const int lm = lane & 7;
    const int ln = lane >> 3;
    const int wm = (wid & 1) * 64;
    const int wn = (wid >> 1) * 32;
    const int bm = blockIdx.y * BM;
    const int bn = blockIdx.x * BN;
    const int z  = blockIdx.z;
    const int kbase = z * KC;

    const int m0 = wm + lm * 4, m1 = m0 + 32;
    const int n0 = wn + ln * 4, n1 = n0 + 16;

    float acc[2][2][4][4];
#pragma unroll
    for (int mi = 0; mi < 2; mi++)
#pragma unroll
        for (int ni = 0; ni < 2; ni++)
#pragma unroll
            for (int i = 0; i < 4; i++)
#pragma unroll
                for (int j = 0; j < 4; j++) acc[mi][ni][i][j] = 0.0f;

    // staging: 1024 16B-chunks per tile per array; 4 per thread each
    const float* srcA[4];
    const float* srcB[4];
    uint32_t dA[4], dB[4];
#pragma unroll
    for (int f = 0; f < 4; f++) {
        const int id = tid + 256 * f;
        const int k = id >> 5;              // 0..31
        const int c4 = (id & 31) << 2;      // 0..124
        srcA[f] = AT + (size_t)(kbase + k) * B_ + bm + c4;
        srcB[f] = BT + (size_t)(kbase + k) * N_ + bn + c4;
        dA[f] = smb + (uint32_t)(k * STR + c4) * 4u;
        dB[f] = smb + (uint32_t)(2 * BK * STR + k * STR + c4) * 4u;
    }
    const uint32_t bufoff = (uint32_t)(BK * STR * 4);   // bytes per buffer

    // prologue: stage tile 0 into buf 0
#pragma unroll
    for (int f = 0; f < 4; f++) { cpa16(dA[f], srcA[f]); cpa16(dB[f], srcB[f]); }
    cpa_commit();

    for (int t = 0; t < NT; t++) {
        const int buf = t & 1;
        if (t + 1 < NT) {
            const uint32_t bo = ((t + 1) & 1) * bufoff;
            const size_t koA = (size_t)(t + 1) * BK * B_;
            const size_t koB = (size_t)(t + 1) * BK * N_;
#pragma unroll
            for (int f = 0; f < 4; f++) {
                cpa16(dA[f] + bo, srcA[f] + koA);
                cpa16(dB[f] + bo, srcB[f] + koB);
            }
            cpa_commit();
            asm volatile("cp.async.wait_group 1;" ::: "memory");
        } else {
            asm volatile("cp.async.wait_group 0;" ::: "memory");
        }
        __syncthreads();

        const float* as = sm + buf * BK * STR;
        const float* bs = sm + 2 * BK * STR + buf * BK * STR;
#pragma unroll 8
        for (int kk = 0; kk < BK; kk++) {
            const float4 a0 = *(const float4*)&as[kk * STR + m0];
            const float4 a1 = *(const float4*)&as[kk * STR + m1];
            const float4 b0 = *(const float4*)&bs[kk * STR + n0];
            const float4 b1 = *(const float4*)&bs[kk * STR + n1];
            const float am[2][4] = { { a0.x, a0.y, a0.z, a0.w },
                                     { a1.x, a1.y, a1.z, a1.w } };
            const float bn_[2][4] = { { b0.x, b0.y, b0.z, b0.w },
                                      { b1.x, b1.y, b1.z, b1.w } };
#pragma unroll
            for (int mi = 0; mi < 2; mi++)
#pragma unroll
                for (int ni = 0; ni < 2; ni++)
#pragma unroll
                    for (int i = 0; i < 4; i++)
#pragma unroll
                        for (int j = 0; j < 4; j++)
                            acc[mi][ni][i][j] =
                                __fmaf_rn(am[mi][i], bn_[ni][j], acc[mi][ni][i][j]);
        }
        __syncthreads();   // protect buf before it is restaged at t+1
    }

    float* Pz = g_part + (size_t)z * SZ;
#pragma unroll
    for (int mi = 0; mi < 2; mi++) {
#pragma unroll
        for (int i = 0; i < 4; i++) {
            const int row = bm + wm + mi * 32 + lm * 4 + i;
#pragma unroll
            for (int ni = 0; ni < 2; ni++) {
                const int col = bn + wn + ni * 16 + ln * 4;
                float4 v = { acc[mi][ni][i][0], acc[mi][ni][i][1],
                             acc[mi][ni][i][2], acc[mi][ni][i][3] };
                *(float4*)&Pz[(size_t)row * N_ + col] = v;
            }
        }
    }
}

// ---------------------------------------------------------------------------
// ff reduce: fold partials (ascending RN, exact R11 sequence) + bias -> g_ff
// ---------------------------------------------------------------------------
__global__ void __launch_bounds__(256)
reduce_ff(const float* __restrict__ bias) {
    const int i = blockIdx.x * blockDim.x + threadIdx.x;
    if (i >= SZ) return;
    float acc = 0.0f;
#pragma unroll
    for (int zz = 0; zz < NSLICE; zz++)
        acc = __fadd_rn(acc, g_part[(size_t)zz * SZ + i]);
    g_ff[i] = __fadd_rn(acc, bias[i & (N_ - 1)]);
}

// ---------------------------------------------------------------------------
// SNN step reduce: fold partials + bias -> mem_r, full state update (per-op
// RN), write spk row-major AND transposed (via smem tile) for next GEMM.
// ZACC=true: partials are exactly zero (t=0, spk==0) — skip reads.
// ---------------------------------------------------------------------------
template <bool ZACC>
__global__ void __launch_bounds__(256)
reduce_snn(const float* __restrict__ bias, float* __restrict__ ssum,
           const int* __restrict__ sw, int step) {
    if (step >= *sw) return;
    __shared__ float tile[32][33];
    const int n0 = blockIdx.x * 32, m0 = blockIdx.y * 32;
    const int tx = threadIdx.x & 31, ty = threadIdx.x >> 5;   // ty 0..7
    const float b = bias[n0 + tx];
#pragma unroll
    for (int r = 0; r < 4; r++) {
        const int ml = ty + 8 * r;
        const size_t i = (size_t)(m0 + ml) * N_ + n0 + tx;
        float acc = 0.0f;
        if (!ZACC) {
#pragma unroll
            for (int zz = 0; zz < NSLICE; zz++)
                acc = __fadd_rn(acc, g_part[(size_t)zz * SZ + i]);
        }
        const float mr = __fadd_rn(acc, b);
        float s = g_spk[i];
        float m = g_mem[i];
        float a = g_ath[i];
        a = __fadd_rn(__fmul_rn(0.9f, a), __fmul_rn(0.5f, s));
        float mff = __fmul_rn(m, 0.2f);
        mff = __fmul_rn(mff, __fsub_rn(1.0f, s));
        mff = __fadd_rn(mff, g_ff[i]);
        mff = __fsub_rn(mff, __fmul_rn(a, 0.2f));
        const float sff = (mff > 0.5f) ? 1.0f : 0.0f;
        const float sr  = (mr  > 0.5f) ? 1.0f : 0.0f;
        g_mem[i] = __fadd_rn(mff, mr);
        g_ath[i] = a;
        const float sn = __fadd_rn(sff, sr);
        g_spk[i] = sn;
        ssum[i] = __fadd_rn(ssum[i], sn);
        tile[ml][tx] = sn;
    }
    __syncthreads();
#pragma unroll
    for (int r = 0; r < 4; r++) {
        const int nl = ty + 8 * r;
        g_spkT[(size_t)(n0 + nl) * B_ + m0 + tx] = tile[tx][nl];
    }
}

// ---------------------------------------------------------------------------
// Launch. Inputs: x, W_fc, b_fc, W_rec, b_rec, rec_mask, spike_window
// ---------------------------------------------------------------------------
extern "C" void kernel_launch(void* const* d_in, const int* in_sizes, int n_in,
                              void* d_out, int out_size) {
    const float* x        = (const float*)d_in[0];
    const float* W_fc     = (const float*)d_in[1];
    const float* b_fc     = (const float*)d_in[2];
    const float* W_rec    = (const float*)d_in[3];
    const float* b_rec    = (const float*)d_in[4];
    const int*   rec_mask = (const int*)d_in[5];
    const int*   sw       = (const int*)d_in[6];
    float*       out      = (float*)d_out;

    float *WrT, *WfcT, *xT, *spkT;
    cudaGetSymbolAddress((void**)&WrT,  g_WrT);
    cudaGetSymbolAddress((void**)&WfcT, g_WfcT);
    cudaGetSymbolAddress((void**)&xT,   g_xT);
    cudaGetSymbolAddress((void**)&spkT, g_spkT);

    static int smem_set = 0;
    if (!smem_set) {
        cudaFuncSetAttribute(slice_gemm,
                             cudaFuncAttributeMaxDynamicSharedMemorySize,
                             SMEM_GEMM);
        smem_set = 1;
    }

    dim3 tt(32, 8);
    transpose_mask_kernel<<<dim3(K_ / 32, N_ / 32), tt>>>(W_fc, nullptr, WfcT, N_, K_);
    transpose_mask_kernel<<<dim3(N_ / 32, N_ / 32), tt>>>(W_rec, rec_mask, WrT, N_, N_);
    transpose_mask_kernel<<<dim3(K_ / 32, B_ / 32), tt>>>(x, nullptr, xT, B_, K_);

    init_zero_kernel<<<(SZ + 255) / 256, 256>>>(out);

    dim3 gg(N_ / BN, B_ / BM, NSLICE);        // (16, 4, 4) = 256 CTAs
    dim3 rg(N_ / 32, B_ / 32);                // (64, 16) reduce tiles

    // ff = x @ W_fc^T + b_fc  (loop-invariant)
    slice_gemm<<<gg, 256, SMEM_GEMM>>>(xT, WfcT, sw, -1);
    reduce_ff<<<(SZ + 255) / 256, 256>>>(b_fc);

    // t = 0: spk == 0 -> every chain is exactly 0.0; skip the GEMM.
    reduce_snn<true><<<rg, 256>>>(b_rec, out, sw, 0);

    // t = 1..15: split-K GEMM on spk^T + fused reduce/SNN
    for (int t = 1; t < NSTEPS; t++) {
        slice_gemm<<<gg, 256, SMEM_GEMM>>>(spkT, WrT, sw, t);
        reduce_snn<false><<<rg, 256>>>(b_rec, out, sw, t);
    }
}

// round 16
// speedup vs baseline: 2.3956x; 1.0980x over previous
#include <cuda_runtime.h>
#include <cstdint>

// Problem dims (fixed by setup_inputs)
#define B_ 512
#define N_ 2048   // OUT
#define K_ 2048   // IN
#define NSTEPS 16
// PROVEN (R11, rel_err = 0.0): reference association = fp32, K split in 4
// quarters of 512; each quarter a continuous ascending FFMA chain from zero;
// quarter-partials folded sequentially (one RN add each, ascending order).
#define KC 512
#define NSLICE (K_ / KC)   // 4
#define SZ (B_ * N_)

// GEMM tiling
#define BM 128
#define BN 128
#define BK 32
#define NT (KC / BK)       // 16 k-tiles per slice
#define STR 132            // smem row stride (floats), padded
#define SMEM_GEMM (2 * 2 * BK * STR * 4)   // A+B double-buffered = 67584 B

// Scratch (static __device__: no allocation allowed)
__device__ float g_WrT[(size_t)N_ * N_];   // (W_rec*mask)^T [k][n]
__device__ float g_WfcT[(size_t)K_ * N_];  // W_fc^T [k][n]
__device__ float g_xT[(size_t)K_ * B_];    // x^T [k][m]
__device__ float g_spkT[(size_t)N_ * B_];  // spk^T [k][m] (GEMM A operand)
__device__ float g_part[(size_t)NSLICE * SZ];  // split-K partials (16MB)
__device__ float g_ff[SZ];
__device__ float g_mem[SZ];
__device__ float g_ath[SZ];
__device__ float g_spk[SZ];                // row-major spikes (state)

// ---------------------------------------------------------------------------
// Packed f32x2 helpers (Blackwell FFMA2 path — each lane is an exact IEEE RN
// FMA, identical to __fmaf_rn; association per output unchanged)
// ---------------------------------------------------------------------------
static __device__ __forceinline__ void ffma2(unsigned long long& d,
                                             unsigned long long a,
                                             unsigned long long b) {
    asm("fma.rn.f32x2 %0, %1, %2, %0;" : "+l"(d) : "l"(a), "l"(b));
}
static __device__ __forceinline__ unsigned long long bcast2(float x) {
    unsigned long long r;
    asm("mov.b64 %0, {%1, %1};" : "=l"(r) : "f"(x));
    return r;
}
static __device__ __forceinline__ void unpack2(unsigned long long v,
                                               float& lo, float& hi) {
    asm("mov.b64 {%0, %1}, %2;" : "=f"(lo), "=f"(hi) : "l"(v));
}

// ---------------------------------------------------------------------------
// Transpose (optionally fused with integer mask multiply)
// ---------------------------------------------------------------------------
__global__ void transpose_mask_kernel(const float* __restrict__ src,
                                      const int* __restrict__ mask,
                                      float* __restrict__ dst, int R, int C) {
    __shared__ float tile[32][33];
    int c0 = blockIdx.x * 32, r0 = blockIdx.y * 32;
#pragma unroll
    for (int i = 0; i < 32; i += 8) {
        int r = r0 + threadIdx.y + i;
        int c = c0 + threadIdx.x;
        float v = src[(size_t)r * C + c];
        if (mask) v *= (float)mask[(size_t)r * C + c];
        tile[threadIdx.y + i][threadIdx.x] = v;
    }
    __syncthreads();
#pragma unroll
    for (int i = 0; i < 32; i += 8) {
        int r = c0 + threadIdx.y + i;
        int c = r0 + threadIdx.x;
        dst[(size_t)r * R + c] = tile[threadIdx.x][threadIdx.y + i];
    }
}

__global__ void init_zero_kernel(float* __restrict__ out) {
    int i = blockIdx.x * blockDim.x + threadIdx.x;
    if (i < SZ) {
        g_mem[i] = 0.0f;
        g_ath[i] = 0.0f;
        g_spk[i] = 0.0f;
        out[i]   = 0.0f;
    }
}

// ---------------------------------------------------------------------------
// cp.async helpers
// ---------------------------------------------------------------------------
static __device__ __forceinline__ void cpa16(uint32_t dst, const float* src) {
    asm volatile("cp.async.cg.shared.global [%0], [%1], 16;"
                 :: "r"(dst), "l"(src));
}
static __device__ __forceinline__ void cpa_commit() {
    asm volatile("cp.async.commit_group;" ::: "memory");
}

// ---------------------------------------------------------------------------
// Split-K slice SGEMM (operands pre-transposed to [k][.]):
//   part(m,n,z) = FMA chain over k ascending in [z*512,(z+1)*512) from zero.
// BM=BN=128, BK=32, 8x8/thread via packed f32x2 (32 FFMA2/kk), 256 threads,
// grid (16,4,4)=256 CTAs, 2 CTAs/SM. cp.async double-buffered staging.
// ---------------------------------------------------------------------------
__global__ void __launch_bounds__(256, 2)
slice_gemm(const float* __restrict__ AT, const float* __restrict__ BT,
           const int* __restrict__ sw, int step) {
    if (step >= *sw) return;   // uniform

    extern __shared__ float sm[];
    const uint32_t smb = (uint32_t)__cvta_generic_to_shared(sm);
    const int tid = threadIdx.x;
    const int wid = tid >> 5;
    const int lane = tid & 31;
    const int lm = lane & 7;
    const int ln = lane >> 3;
    const int wm = (wid & 1) * 64;
    const int wn = (wid >> 1) * 32;
    const int bm = blockIdx.y * BM;
    const int bn = blockIdx.x * BN;
    const int z  = blockIdx.z;
    const int kbase = z * KC;

    const int m0 = wm + lm * 4, m1 = m0 + 32;
    const int n0 = wn + ln * 4, n1 = n0 + 16;

    // packed accumulators: [mi][ni][i][jp], lanes = (col 2*jp, col 2*jp+1)
    unsigned long long acc2[2][2][4][2];
#pragma unroll
    for (int mi = 0; mi < 2; mi++)
#pragma unroll
        for (int ni = 0; ni < 2; ni++)
#pragma unroll
            for (int i = 0; i < 4; i++)
#pragma unroll
                for (int jp = 0; jp < 2; jp++) acc2[mi][ni][i][jp] = 0ull;

    // staging: 1024 16B-chunks per tile per array; 4 per thread each
    const float* srcA[4];
    const float* srcB[4];
    uint32_t dA[4], dB[4];
#pragma unroll
    for (int f = 0; f < 4; f++) {
        const int id = tid + 256 * f;
        const int k = id >> 5;              // 0..31
        const int c4 = (id & 31) << 2;      // 0..124
        srcA[f] = AT + (size_t)(kbase + k) * B_ + bm + c4;
        srcB[f] = BT + (size_t)(kbase + k) * N_ + bn + c4;
        dA[f] = smb + (uint32_t)(k * STR + c4) * 4u;
        dB[f] = smb + (uint32_t)(2 * BK * STR + k * STR + c4) * 4u;
    }
    const uint32_t bufoff = (uint32_t)(BK * STR * 4);   // bytes per buffer

    // prologue: stage tile 0 into buf 0
#pragma unroll
    for (int f = 0; f < 4; f++) { cpa16(dA[f], srcA[f]); cpa16(dB[f], srcB[f]); }
    cpa_commit();

    for (int t = 0; t < NT; t++) {
        const int buf = t & 1;
        if (t + 1 < NT) {
            const uint32_t bo = ((t + 1) & 1) * bufoff;
            const size_t koA = (size_t)(t + 1) * BK * B_;
            const size_t koB = (size_t)(t + 1) * BK * N_;
#pragma unroll
            for (int f = 0; f < 4; f++) {
                cpa16(dA[f] + bo, srcA[f] + koA);
                cpa16(dB[f] + bo, srcB[f] + koB);
            }
            cpa_commit();
            asm volatile("cp.async.wait_group 1;" ::: "memory");
        } else {
            asm volatile("cp.async.wait_group 0;" ::: "memory");
        }
        __syncthreads();

        const float* as = sm + buf * BK * STR;
        const float* bs = sm + 2 * BK * STR + buf * BK * STR;
#pragma unroll 8
        for (int kk = 0; kk < BK; kk++) {
            const float4 a0 = *(const float4*)&as[kk * STR + m0];
            const float4 a1 = *(const float4*)&as[kk * STR + m1];
            const unsigned long long* bq0 =
                (const unsigned long long*)&bs[kk * STR + n0];
            const unsigned long long* bq1 =
                (const unsigned long long*)&bs[kk * STR + n1];
            const unsigned long long ap[2][4] = {
                { bcast2(a0.x), bcast2(a0.y), bcast2(a0.z), bcast2(a0.w) },
                { bcast2(a1.x), bcast2(a1.y), bcast2(a1.z), bcast2(a1.w) } };
            const unsigned long long bp[2][2] = { { bq0[0], bq0[1] },
                                                  { bq1[0], bq1[1] } };
#pragma unroll
            for (int mi = 0; mi < 2; mi++)
#pragma unroll
                for (int ni = 0; ni < 2; ni++)
#pragma unroll
                    for (int i = 0; i < 4; i++)
#pragma unroll
                        for (int jp = 0; jp < 2; jp++)
                            ffma2(acc2[mi][ni][i][jp], ap[mi][i], bp[ni][jp]);
        }
        __syncthreads();   // protect buf before it is restaged at t+1
    }

    float* Pz = g_part + (size_t)z * SZ;
#pragma unroll
    for (int mi = 0; mi < 2; mi++) {
#pragma unroll
        for (int i = 0; i < 4; i++) {
            const int row = bm + wm + mi * 32 + lm * 4 + i;
#pragma unroll
            for (int ni = 0; ni < 2; ni++) {
                const int col = bn + wn + ni * 16 + ln * 4;
                float4 v;
                unpack2(acc2[mi][ni][i][0], v.x, v.y);
                unpack2(acc2[mi][ni][i][1], v.z, v.w);
                *(float4*)&Pz[(size_t)row * N_ + col] = v;
            }
        }
    }
}

// ---------------------------------------------------------------------------
// ff reduce: fold partials (ascending RN, exact R11 sequence) + bias -> g_ff
// ---------------------------------------------------------------------------
__global__ void __launch_bounds__(256)
reduce_ff(const float* __restrict__ bias) {
    const int i = blockIdx.x * blockDim.x + threadIdx.x;
    if (i >= SZ) return;
    float acc = 0.0f;
#pragma unroll
    for (int zz = 0; zz < NSLICE; zz++)
        acc = __fadd_rn(acc, g_part[(size_t)zz * SZ + i]);
    g_ff[i] = __fadd_rn(acc, bias[i & (N_ - 1)]);
}

// ---------------------------------------------------------------------------
// SNN step reduce: fold partials + bias -> mem_r, full state update (per-op
// RN), write spk row-major AND transposed (via smem tile) for next GEMM.
// ZACC=true: partials are exactly zero (t=0, spk==0) — skip reads.
// ---------------------------------------------------------------------------
template <bool ZACC>
__global__ void __launch_bounds__(256)
reduce_snn(const float* __restrict__ bias, float* __restrict__ ssum,
           const int* __restrict__ sw, int step) {
    if (step >= *sw) return;
    __shared__ float tile[32][33];
    const int n0 = blockIdx.x * 32, m0 = blockIdx.y * 32;
    const int tx = threadIdx.x & 31, ty = threadIdx.x >> 5;   // ty 0..7
    const float b = bias[n0 + tx];
#pragma unroll
    for (int r = 0; r < 4; r++) {
        const int ml = ty + 8 * r;
        const size_t i = (size_t)(m0 + ml) * N_ + n0 + tx;
        float acc = 0.0f;
        if (!ZACC) {
#pragma unroll
            for (int zz = 0; zz < NSLICE; zz++)
                acc = __fadd_rn(acc, g_part[(size_t)zz * SZ + i]);
        }
        const float mr = __fadd_rn(acc, b);
        float s = g_spk[i];
        float m = g_mem[i];
        float a = g_ath[i];
        a = __fadd_rn(__fmul_rn(0.9f, a), __fmul_rn(0.5f, s));
        float mff = __fmul_rn(m, 0.2f);
        mff = __fmul_rn(mff, __fsub_rn(1.0f, s));
        mff = __fadd_rn(mff, g_ff[i]);
        mff = __fsub_rn(mff, __fmul_rn(a, 0.2f));
        const float sff = (mff > 0.5f) ? 1.0f : 0.0f;
        const float sr  = (mr  > 0.5f) ? 1.0f : 0.0f;
        g_mem[i] = __fadd_rn(mff, mr);
        g_ath[i] = a;
        const float sn = __fadd_rn(sff, sr);
        g_spk[i] = sn;
        ssum[i] = __fadd_rn(ssum[i], sn);
        tile[ml][tx] = sn;
    }
    __syncthreads();
#pragma unroll
    for (int r = 0; r < 4; r++) {
        const int nl = ty + 8 * r;
        g_spkT[(size_t)(n0 + nl) * B_ + m0 + tx] = tile[tx][nl];
    }
}

// ---------------------------------------------------------------------------
// Launch. Inputs: x, W_fc, b_fc, W_rec, b_rec, rec_mask, spike_window
// ---------------------------------------------------------------------------
extern "C" void kernel_launch(void* const* d_in, const int* in_sizes, int n_in,
                              void* d_out, int out_size) {
    const float* x        = (const float*)d_in[0];
    const float* W_fc     = (const float*)d_in[1];
    const float* b_fc     = (const float*)d_in[2];
    const float* W_rec    = (const float*)d_in[3];
    const float* b_rec    = (const float*)d_in[4];
    const int*   rec_mask = (const int*)d_in[5];
    const int*   sw       = (const int*)d_in[6];
    float*       out      = (float*)d_out;

    float *WrT, *WfcT, *xT, *spkT;
    cudaGetSymbolAddress((void**)&WrT,  g_WrT);
    cudaGetSymbolAddress((void**)&WfcT, g_WfcT);
    cudaGetSymbolAddress((void**)&xT,   g_xT);
    cudaGetSymbolAddress((void**)&spkT, g_spkT);

    static int smem_set = 0;
    if (!smem_set) {
        cudaFuncSetAttribute(slice_gemm,
                             cudaFuncAttributeMaxDynamicSharedMemorySize,
                             SMEM_GEMM);
        smem_set = 1;
    }

    dim3 tt(32, 8);
    transpose_mask_kernel<<<dim3(K_ / 32, N_ / 32), tt>>>(W_fc, nullptr, WfcT, N_, K_);
    transpose_mask_kernel<<<dim3(N_ / 32, N_ / 32), tt>>>(W_rec, rec_mask, WrT, N_, N_);
    transpose_mask_kernel<<<dim3(K_ / 32, B_ / 32), tt>>>(x, nullptr, xT, B_, K_);

    init_zero_kernel<<<(SZ + 255) / 256, 256>>>(out);

    dim3 gg(N_ / BN, B_ / BM, NSLICE);        // (16, 4, 4) = 256 CTAs
    dim3 rg(N_ / 32, B_ / 32);                // (64, 16) reduce tiles

    // ff = x @ W_fc^T + b_fc  (loop-invariant)
    slice_gemm<<<gg, 256, SMEM_GEMM>>>(xT, WfcT, sw, -1);
    reduce_ff<<<(SZ + 255) / 256, 256>>>(b_fc);

    // t = 0: spk == 0 -> every chain is exactly 0.0; skip the GEMM.
    reduce_snn<true><<<rg, 256>>>(b_rec, out, sw, 0);

    // t = 1..15: split-K GEMM on spk^T + fused reduce/SNN
    for (int t = 1; t < NSTEPS; t++) {
        slice_gemm<<<gg, 256, SMEM_GEMM>>>(spkT, WrT, sw, t);
        reduce_snn<false><<<rg, 256>>>(b_rec, out, sw, t);
    }
}